// round 2
// baseline (speedup 1.0000x reference)
#include <cuda_runtime.h>
#include <cuda_fp16.h>
#include <math.h>

#define C 32
#define LAYERS 4
#define NFIX 2
#define MAXN 100000
#define MAXE 1600000
#define LC (LAYERS * C)   // 128

// Scratch (device globals — no runtime allocation allowed)
__device__ __align__(256) __half g_dZ[(size_t)MAXN * LC];   // [N][L][C] fp16
__device__ __align__(256) float  g_agg[(size_t)MAXN * LC];  // [N][L][C] fp32
__device__ __align__(256) float  g_Z[(size_t)LAYERS * MAXN * C]; // [L][N][C]

__device__ __forceinline__ float silu_f(float x) {
    // silu(x) = x * sigmoid(x) = 0.5*x*tanh(0.5x) + 0.5*x   (1 MUFU)
    float t;
    asm("tanh.approx.f32 %0, %1;" : "=f"(t) : "f"(0.5f * x));
    float hx = 0.5f * x;
    return fmaf(hx, t, hx);
}

// ---------------------------------------------------------------------------
// Kernel 1: per (node, layer):  h = silu([Z_l, f] @ Kf_l);  dZ = h @ K_l
// 2 nodes per thread (weights read once per 2 nodes), float4 SMEM reads.
// Writes dZ as fp16 in node-major [N][L][C]; zeroes agg.
// grid: (ceil(N/512), L), block 256.
// ---------------------------------------------------------------------------
__global__ __launch_bounds__(256) void node_forward_kernel(
        const float* __restrict__ Z,
        const float* __restrict__ f,
        const float* __restrict__ Kf,
        const float* __restrict__ K,
        __half* __restrict__ dZ,
        float* __restrict__ agg,
        int N, int useZ)
{
    __shared__ float4 Kfs[2 * C * C / 4];  // 512 float4 = 8 KB
    __shared__ float4 Ks[C * C / 4];       // 256 float4 = 4 KB
    const int l = blockIdx.y;
    {
        const float4* Kfl = (const float4*)(Kf + (size_t)l * 2 * C * C);
        const float4* Kl  = (const float4*)(K  + (size_t)l * C * C);
        for (int i = threadIdx.x; i < 2 * C * C / 4; i += blockDim.x) Kfs[i] = Kfl[i];
        for (int i = threadIdx.x; i < C * C / 4;     i += blockDim.x) Ks[i]  = Kl[i];
    }
    __syncthreads();

    const int n0 = blockIdx.x * 512 + threadIdx.x;
    const int n1 = n0 + 256;
    if (n0 >= N) return;
    const bool v1 = (n1 < N);

    float h0[C], h1[C];
#pragma unroll
    for (int c = 0; c < C; c++) { h0[c] = 0.f; h1[c] = 0.f; }

    // ---- h += Z @ Kf[:32]  (skipped on first fixpoint iter: Z == 0) ----
    if (useZ) {
        const float4* z0 = (const float4*)(Z + ((size_t)l * N + n0) * C);
        const float4* z1 = (const float4*)(Z + ((size_t)l * N + n1) * C);
#pragma unroll
        for (int k4 = 0; k4 < 8; k4++) {
            float4 a = z0[k4];
            float4 b = v1 ? z1[k4] : make_float4(0.f, 0.f, 0.f, 0.f);
            float za[4] = {a.x, a.y, a.z, a.w};
            float zb[4] = {b.x, b.y, b.z, b.w};
#pragma unroll
            for (int kk = 0; kk < 4; kk++) {
                const float4* wr = &Kfs[(k4 * 4 + kk) * 8];
                float sa = za[kk], sb = zb[kk];
#pragma unroll
                for (int c4 = 0; c4 < 8; c4++) {
                    float4 w = wr[c4];
                    h0[c4*4+0] = fmaf(sa, w.x, h0[c4*4+0]);
                    h0[c4*4+1] = fmaf(sa, w.y, h0[c4*4+1]);
                    h0[c4*4+2] = fmaf(sa, w.z, h0[c4*4+2]);
                    h0[c4*4+3] = fmaf(sa, w.w, h0[c4*4+3]);
                    h1[c4*4+0] = fmaf(sb, w.x, h1[c4*4+0]);
                    h1[c4*4+1] = fmaf(sb, w.y, h1[c4*4+1]);
                    h1[c4*4+2] = fmaf(sb, w.z, h1[c4*4+2]);
                    h1[c4*4+3] = fmaf(sb, w.w, h1[c4*4+3]);
                }
            }
        }
    }
    // ---- h += f @ Kf[32:] ----
    {
        const float4* f0 = (const float4*)(f + (size_t)n0 * C);
        const float4* f1 = (const float4*)(f + (size_t)n1 * C);
#pragma unroll
        for (int k4 = 0; k4 < 8; k4++) {
            float4 a = f0[k4];
            float4 b = v1 ? f1[k4] : make_float4(0.f, 0.f, 0.f, 0.f);
            float za[4] = {a.x, a.y, a.z, a.w};
            float zb[4] = {b.x, b.y, b.z, b.w};
#pragma unroll
            for (int kk = 0; kk < 4; kk++) {
                const float4* wr = &Kfs[(C + k4 * 4 + kk) * 8];
                float sa = za[kk], sb = zb[kk];
#pragma unroll
                for (int c4 = 0; c4 < 8; c4++) {
                    float4 w = wr[c4];
                    h0[c4*4+0] = fmaf(sa, w.x, h0[c4*4+0]);
                    h0[c4*4+1] = fmaf(sa, w.y, h0[c4*4+1]);
                    h0[c4*4+2] = fmaf(sa, w.z, h0[c4*4+2]);
                    h0[c4*4+3] = fmaf(sa, w.w, h0[c4*4+3]);
                    h1[c4*4+0] = fmaf(sb, w.x, h1[c4*4+0]);
                    h1[c4*4+1] = fmaf(sb, w.y, h1[c4*4+1]);
                    h1[c4*4+2] = fmaf(sb, w.z, h1[c4*4+2]);
                    h1[c4*4+3] = fmaf(sb, w.w, h1[c4*4+3]);
                }
            }
        }
    }
#pragma unroll
    for (int c = 0; c < C; c++) { h0[c] = silu_f(h0[c]); h1[c] = silu_f(h1[c]); }

    // ---- dZ = h @ K, in two 16-channel passes (register pressure) ----
    __half* dz0 = dZ + ((size_t)n0 * LAYERS + l) * C;
    __half* dz1 = dZ + ((size_t)n1 * LAYERS + l) * C;
#pragma unroll
    for (int half = 0; half < 2; half++) {
        float d0[16], d1[16];
#pragma unroll
        for (int c = 0; c < 16; c++) { d0[c] = 0.f; d1[c] = 0.f; }
#pragma unroll
        for (int k = 0; k < C; k++) {
            const float4* wr = &Ks[k * 8 + half * 4];
            float sa = h0[k], sb = h1[k];
#pragma unroll
            for (int c4 = 0; c4 < 4; c4++) {
                float4 w = wr[c4];
                d0[c4*4+0] = fmaf(sa, w.x, d0[c4*4+0]);
                d0[c4*4+1] = fmaf(sa, w.y, d0[c4*4+1]);
                d0[c4*4+2] = fmaf(sa, w.z, d0[c4*4+2]);
                d0[c4*4+3] = fmaf(sa, w.w, d0[c4*4+3]);
                d1[c4*4+0] = fmaf(sb, w.x, d1[c4*4+0]);
                d1[c4*4+1] = fmaf(sb, w.y, d1[c4*4+1]);
                d1[c4*4+2] = fmaf(sb, w.z, d1[c4*4+2]);
                d1[c4*4+3] = fmaf(sb, w.w, d1[c4*4+3]);
            }
        }
        union { __half2 h2[8]; uint4 u[2]; } p0, p1;
#pragma unroll
        for (int i = 0; i < 8; i++) {
            p0.h2[i] = __float22half2_rn(make_float2(d0[2*i], d0[2*i+1]));
            p1.h2[i] = __float22half2_rn(make_float2(d1[2*i], d1[2*i+1]));
        }
        ((uint4*)dz0)[half * 2 + 0] = p0.u[0];
        ((uint4*)dz0)[half * 2 + 1] = p0.u[1];
        if (v1) {
            ((uint4*)dz1)[half * 2 + 0] = p1.u[0];
            ((uint4*)dz1)[half * 2 + 1] = p1.u[1];
        }
    }

    // ---- zero agg rows for this (n, l) ----
    float4* a0 = (float4*)(agg + ((size_t)n0 * LAYERS + l) * C);
    float4* a1 = (float4*)(agg + ((size_t)n1 * LAYERS + l) * C);
    const float4 z4 = make_float4(0.f, 0.f, 0.f, 0.f);
#pragma unroll
    for (int c4 = 0; c4 < 8; c4++) {
        a0[c4] = z4;
        if (v1) a1[c4] = z4;
    }
}

// ---------------------------------------------------------------------------
// Kernel 2: edges. 16 threads per edge, 8 fp16 channels each (all 4 layers in
// the contiguous 256B node row).  g = silu(w*(dZ[s]-dZ[t])); red.v4 -> agg[s].
// Edge meta loaded once per edge (leader lane) and shfl-broadcast.
// ---------------------------------------------------------------------------
__global__ __launch_bounds__(256) void edge_kernel(
        const int* __restrict__ ei,
        const float* __restrict__ ew,
        const __half* __restrict__ dZ,
        float* __restrict__ agg,
        int E)
{
    const int idx  = blockIdx.x * blockDim.x + threadIdx.x;
    const int e    = idx >> 4;
    const int sub  = idx & 15;
    const int lane = threadIdx.x & 31;
    const int leader = lane & 16;            // 0 or 16
    const int ec   = (e < E) ? e : (E - 1);

    int s = 0, t = 0; float w = 0.f;
    if (lane == leader) {
        s = __ldg(ei + ec);
        t = __ldg(ei + E + ec);
        w = __ldg(ew + ec);
    }
    s = __shfl_sync(0xffffffffu, s, leader);
    t = __shfl_sync(0xffffffffu, t, leader);
    w = __shfl_sync(0xffffffffu, w, leader);

    const uint4* ps = (const uint4*)(dZ + (size_t)s * LC) + sub;
    const uint4* pt = (const uint4*)(dZ + (size_t)t * LC) + sub;
    uint4 av = __ldg(ps);
    uint4 bv = __ldg(pt);

    union { uint4 u; __half2 h2[4]; } ua, ub;
    ua.u = av; ub.u = bv;

    float g[8];
#pragma unroll
    for (int i = 0; i < 4; i++) {
        float2 fa = __half22float2(ua.h2[i]);
        float2 fb = __half22float2(ub.h2[i]);
        g[2*i+0] = silu_f(w * (fa.x - fb.x));
        g[2*i+1] = silu_f(w * (fa.y - fb.y));
    }

    if (e < E) {
        float* dst = agg + (size_t)s * LC + sub * 8;
        asm volatile("red.global.add.v4.f32 [%0], {%1, %2, %3, %4};"
                     :: "l"(dst), "f"(g[0]), "f"(g[1]), "f"(g[2]), "f"(g[3])
                     : "memory");
        asm volatile("red.global.add.v4.f32 [%0], {%1, %2, %3, %4};"
                     :: "l"(dst + 4), "f"(g[4]), "f"(g[5]), "f"(g[6]), "f"(g[7])
                     : "memory");
    }
}

// ---------------------------------------------------------------------------
// Kernel 3: warp per node.  Y_l = -(agg_l @ K_l^T) (+X for l=3), then tridiag
// across layers, write Z (and optional Z[-1]).
// ---------------------------------------------------------------------------
__global__ __launch_bounds__(256) void tridiag_kernel(
        const float* __restrict__ agg,
        const float* __restrict__ K,
        const float* __restrict__ X,
        float* __restrict__ Zout,
        float* __restrict__ lastOut,
        int N)
{
    __shared__ float KT[LAYERS][C][C];  // KT[l][j][c] = K[l][c][j], 16 KB
    for (int i = threadIdx.x; i < LAYERS * C * C; i += blockDim.x) {
        int l = i >> 10;
        int c = (i >> 5) & 31;
        int j = i & 31;
        KT[l][j][c] = K[i];
    }
    __syncthreads();

    const int gw   = (blockIdx.x * blockDim.x + threadIdx.x) >> 5;
    const int lane = threadIdx.x & 31;
    if (gw >= N) return;

    float Y[LAYERS];
#pragma unroll
    for (int l = 0; l < LAYERS; l++) {
        float av  = agg[((size_t)gw * LAYERS + l) * C + lane];
        float acc = 0.f;
#pragma unroll
        for (int j = 0; j < C; j++)
            acc = fmaf(__shfl_sync(0xffffffffu, av, j), KT[l][j][lane], acc);
        Y[l] = -acc;
    }
    Y[3] += X[(size_t)gw * C + lane];

    const float s12 = 0.70710678118654752f;  // sqrt(1/2)
    const float s23 = 0.81649658092772603f;  // sqrt(2/3)
    const float s34 = 0.86602540378443865f;  // sqrt(3/4)
    const float s45 = 0.89442719099991588f;  // sqrt(4/5)
    float t0 = s12 * Y[0];
    float t1 = s23 * (s12 * t0 + Y[1]);
    float t2 = s34 * (s23 * t1 + Y[2]);
    float t3 = s45 * (s34 * t2 + Y[3]);
    float w3 = s45 * t3;
    float w2 = s34 * (s34 * w3 + t2);
    float w1 = s23 * (s23 * w2 + t1);
    float w0 = s12 * (s12 * w1 + t0);

    const size_t base = (size_t)gw * C + lane;
    const size_t NC   = (size_t)N * C;
    Zout[0 * NC + base] = w0;
    Zout[1 * NC + base] = w1;
    Zout[2 * NC + base] = w2;
    Zout[3 * NC + base] = w3;
    if (lastOut) lastOut[base] = w3;
}

// ---------------------------------------------------------------------------
extern "C" void kernel_launch(void* const* d_in, const int* in_sizes, int n_in,
                              void* d_out, int out_size)
{
    const float* X  = (const float*)d_in[0];
    const float* f  = (const float*)d_in[1];
    const int*   ei = (const int*)d_in[2];
    const float* ew = (const float*)d_in[3];
    const float* K  = (const float*)d_in[4];
    const float* Kf = (const float*)d_in[5];

    const int N = in_sizes[0] / C;
    const int E = in_sizes[3];

    __half* dZ; float *agg, *Zb;
    cudaGetSymbolAddress((void**)&dZ,  g_dZ);
    cudaGetSymbolAddress((void**)&agg, g_agg);
    cudaGetSymbolAddress((void**)&Zb,  g_Z);

    const size_t NC = (size_t)N * C;
    float* out = (float*)d_out;
    float* Zfinal;
    float* lastPtr;
    if ((size_t)out_size >= (size_t)(LAYERS + 1) * NC) {
        lastPtr = out;            // Z[-1] first
        Zfinal  = out + NC;       // then full Z
    } else if ((size_t)out_size >= (size_t)LAYERS * NC) {
        Zfinal  = out;
        lastPtr = nullptr;
    } else {
        Zfinal  = Zb;
        lastPtr = out;
    }

    dim3 nodeGrid((N + 511) / 512, LAYERS);
    const int edgeBlocks = (E * 16 + 255) / 256;
    const int triBlocks  = (N * 32 + 255) / 256;

    for (int it = 0; it < NFIX; it++) {
        node_forward_kernel<<<nodeGrid, 256>>>(Zb, f, Kf, K, dZ, agg, N, it > 0 ? 1 : 0);
        edge_kernel<<<edgeBlocks, 256>>>(ei, ew, dZ, agg, E);
        const bool last = (it == NFIX - 1);
        tridiag_kernel<<<triBlocks, 256>>>(agg, K, X,
                                           last ? Zfinal : Zb,
                                           last ? lastPtr : nullptr,
                                           N);
    }
}

// round 3
// speedup vs baseline: 2.7048x; 2.7048x over previous
#include <cuda_runtime.h>
#include <cuda_fp16.h>
#include <math.h>

#define C 32
#define LAYERS 4
#define NFIX 2
#define MAXN 100000
#define MAXE 1600000
#define LC (LAYERS * C)   // 128

typedef unsigned long long u64;

// ---------------- device scratch (no runtime allocation allowed) -----------
__device__ __align__(256) __half g_dZ[(size_t)MAXN * LC];        // [N][L][C] fp16
__device__ __align__(256) float  g_Z[(size_t)LAYERS * MAXN * C]; // [L][N][C]
__device__ __align__(16)  uint2  g_rec[MAXE];                    // CSR records (t, w)
__device__ int g_cnt[MAXN];
__device__ int g_S[MAXN];
__device__ int g_rowstart[MAXN + 1];
__device__ int g_cursor[MAXN];
__device__ int g_bsum[512];
__device__ int g_boff[512];

// ---------------- helpers ---------------------------------------------------
__device__ __forceinline__ float silu_f(float x) {
    float t;
    asm("tanh.approx.f32 %0, %1;" : "=f"(t) : "f"(0.5f * x));
    float hx = 0.5f * x;
    return fmaf(hx, t, hx);
}
__device__ __forceinline__ u64 pack2(float a, float b) {
    u64 r; asm("mov.b64 %0, {%1, %2};" : "=l"(r) : "f"(a), "f"(b)); return r;
}
__device__ __forceinline__ void unpack2(u64 v, float& a, float& b) {
    asm("mov.b64 {%0, %1}, %2;" : "=f"(a), "=f"(b) : "l"(v));
}
__device__ __forceinline__ u64 fma2(u64 a, u64 b, u64 c) {
    u64 d; asm("fma.rn.f32x2 %0, %1, %2, %3;" : "=l"(d) : "l"(a), "l"(b), "l"(c));
    return d;
}

// ---------------- CSR build -------------------------------------------------
__global__ void zero_cnt_kernel(int* cnt, int N) {
    int i = blockIdx.x * blockDim.x + threadIdx.x;
    if (i < N) cnt[i] = 0;
}

__global__ void hist_kernel(const int* __restrict__ ei, int* cnt, int E) {
    int e = blockIdx.x * blockDim.x + threadIdx.x;
    if (e < E) atomicAdd(&cnt[__ldg(ei + e)], 1);
}

// 512-thread block inclusive scan; writes per-element inclusive S and block sums
__global__ void scan1_kernel(const int* __restrict__ cnt, int* S, int* bsum, int N) {
    const int i = blockIdx.x * 512 + threadIdx.x;
    const int lane = threadIdx.x & 31, wid = threadIdx.x >> 5;
    int v = (i < N) ? cnt[i] : 0;
    int x = v;
#pragma unroll
    for (int d = 1; d < 32; d <<= 1) {
        int y = __shfl_up_sync(0xffffffffu, x, d);
        if (lane >= d) x += y;
    }
    __shared__ int ws[16];
    if (lane == 31) ws[wid] = x;
    __syncthreads();
    if (wid == 0) {
        int y = (lane < 16) ? ws[lane] : 0;
#pragma unroll
        for (int d = 1; d < 16; d <<= 1) {
            int z = __shfl_up_sync(0xffffffffu, y, d);
            if (lane >= d) y += z;
        }
        if (lane < 16) ws[lane] = y;
    }
    __syncthreads();
    if (wid > 0) x += ws[wid - 1];
    if (i < N) S[i] = x;
    if (threadIdx.x == 511) bsum[blockIdx.x] = x;
}

// single block: exclusive scan of up to 512 block sums
__global__ void scan2_kernel(const int* __restrict__ bsum, int* boff, int nb) {
    const int i = threadIdx.x;
    const int lane = i & 31, wid = i >> 5;
    int v = (i < nb) ? bsum[i] : 0;
    int x = v;
#pragma unroll
    for (int d = 1; d < 32; d <<= 1) {
        int y = __shfl_up_sync(0xffffffffu, x, d);
        if (lane >= d) x += y;
    }
    __shared__ int ws[16];
    if (lane == 31) ws[wid] = x;
    __syncthreads();
    if (wid == 0) {
        int y = (lane < 16) ? ws[lane] : 0;
#pragma unroll
        for (int d = 1; d < 16; d <<= 1) {
            int z = __shfl_up_sync(0xffffffffu, y, d);
            if (lane >= d) y += z;
        }
        if (lane < 16) ws[lane] = y;
    }
    __syncthreads();
    if (wid > 0) x += ws[wid - 1];
    if (i < nb) boff[i] = x - v;   // exclusive
}

__global__ void scan3_kernel(const int* __restrict__ cnt, const int* __restrict__ S,
                             const int* __restrict__ boff,
                             int* rowstart, int* cursor, int N) {
    const int i = blockIdx.x * 512 + threadIdx.x;
    if (i >= N) return;
    int s = S[i] + boff[blockIdx.x];   // inclusive scan, global
    int c = cnt[i];
    rowstart[i] = s - c;
    cursor[i]   = s - c;
    if (i == N - 1) rowstart[N] = s;
}

__global__ void scatter_kernel(const int* __restrict__ ei, const float* __restrict__ ew,
                               int* cursor, uint2* rec, int E) {
    int e = blockIdx.x * blockDim.x + threadIdx.x;
    if (e >= E) return;
    int s = __ldg(ei + e);
    int t = __ldg(ei + E + e);
    float w = __ldg(ew + e);
    int p = atomicAdd(&cursor[s], 1);
    rec[p] = make_uint2((unsigned)t, __float_as_uint(w));
}

// ---------------------------------------------------------------------------
// Node forward: per (node, layer): h = silu([Z_l, f] @ Kf_l); dZ = h @ K_l
// Packed f32x2 FMA; SMEM weights read as ulonglong2 (no repacking).
// dZ written fp16 node-major [N][L][C]. grid: (ceil(N/256), L), block 256.
// ---------------------------------------------------------------------------
__global__ __launch_bounds__(256) void node_forward_kernel(
        const float* __restrict__ Z,
        const float* __restrict__ f,
        const float* __restrict__ Kf,
        const float* __restrict__ K,
        __half* __restrict__ dZ,
        int N, int useZ)
{
    __shared__ __align__(16) float Kfs[2 * C * C];   // 8 KB
    __shared__ __align__(16) float Ks[C * C];        // 4 KB
    const int l = blockIdx.y;
    {
        const float4* Kfl = (const float4*)(Kf + (size_t)l * 2 * C * C);
        const float4* Kl  = (const float4*)(K  + (size_t)l * C * C);
        float4* s0 = (float4*)Kfs;
        float4* s1 = (float4*)Ks;
        for (int i = threadIdx.x; i < 2 * C * C / 4; i += blockDim.x) s0[i] = Kfl[i];
        for (int i = threadIdx.x; i < C * C / 4;     i += blockDim.x) s1[i] = Kl[i];
    }
    __syncthreads();

    const int n = blockIdx.x * blockDim.x + threadIdx.x;
    if (n >= N) return;

    u64 hp[16];
#pragma unroll
    for (int i = 0; i < 16; i++) hp[i] = 0ULL;

    // h += Z @ Kf[:32]
    if (useZ) {
        const float4* zr = (const float4*)(Z + ((size_t)l * N + n) * C);
#pragma unroll
        for (int k4 = 0; k4 < 8; k4++) {
            float4 zv = zr[k4];
            float zs[4] = {zv.x, zv.y, zv.z, zv.w};
#pragma unroll
            for (int kk = 0; kk < 4; kk++) {
                u64 s2 = pack2(zs[kk], zs[kk]);
                const ulonglong2* wr = (const ulonglong2*)&Kfs[(k4 * 4 + kk) * C];
#pragma unroll
                for (int c4 = 0; c4 < 8; c4++) {
                    ulonglong2 w = wr[c4];
                    hp[2 * c4 + 0] = fma2(s2, w.x, hp[2 * c4 + 0]);
                    hp[2 * c4 + 1] = fma2(s2, w.y, hp[2 * c4 + 1]);
                }
            }
        }
    }
    // h += f @ Kf[32:]
    {
        const float4* fr = (const float4*)(f + (size_t)n * C);
#pragma unroll
        for (int k4 = 0; k4 < 8; k4++) {
            float4 fv = fr[k4];
            float fs[4] = {fv.x, fv.y, fv.z, fv.w};
#pragma unroll
            for (int kk = 0; kk < 4; kk++) {
                u64 s2 = pack2(fs[kk], fs[kk]);
                const ulonglong2* wr = (const ulonglong2*)&Kfs[(C + k4 * 4 + kk) * C];
#pragma unroll
                for (int c4 = 0; c4 < 8; c4++) {
                    ulonglong2 w = wr[c4];
                    hp[2 * c4 + 0] = fma2(s2, w.x, hp[2 * c4 + 0]);
                    hp[2 * c4 + 1] = fma2(s2, w.y, hp[2 * c4 + 1]);
                }
            }
        }
    }

    float h[C];
#pragma unroll
    for (int i = 0; i < 16; i++) unpack2(hp[i], h[2 * i], h[2 * i + 1]);
#pragma unroll
    for (int c = 0; c < C; c++) h[c] = silu_f(h[c]);

    // dZ = h @ K
    u64 dp[16];
#pragma unroll
    for (int i = 0; i < 16; i++) dp[i] = 0ULL;
#pragma unroll
    for (int k = 0; k < C; k++) {
        u64 s2 = pack2(h[k], h[k]);
        const ulonglong2* wr = (const ulonglong2*)&Ks[k * C];
#pragma unroll
        for (int c4 = 0; c4 < 8; c4++) {
            ulonglong2 w = wr[c4];
            dp[2 * c4 + 0] = fma2(s2, w.x, dp[2 * c4 + 0]);
            dp[2 * c4 + 1] = fma2(s2, w.y, dp[2 * c4 + 1]);
        }
    }

    union { __half2 h2[16]; uint4 u[4]; } pk;
#pragma unroll
    for (int i = 0; i < 16; i++) {
        float x, y;
        unpack2(dp[i], x, y);
        pk.h2[i] = __float22half2_rn(make_float2(x, y));
    }
    uint4* dzp = (uint4*)(dZ + ((size_t)n * LAYERS + l) * C);
#pragma unroll
    for (int q = 0; q < 4; q++) dzp[q] = pk.u[q];
}

// ---------------------------------------------------------------------------
// Fused edge aggregation (CSR gather, no atomics) + Y = -(agg @ K^T) (+X)
// + tridiagonal solve + Z store. Warp per node; grid-stride over nodes.
// Lane owns 4 halves of the 128-wide [L][C] dZ row: layer=lane/8, cBase=(lane%8)*4.
// ---------------------------------------------------------------------------
__global__ __launch_bounds__(512) void edge_tri_kernel(
        const __half* __restrict__ dZ,
        const uint2* __restrict__ rec,
        const int* __restrict__ rowstart,
        const float* __restrict__ K,
        const float* __restrict__ X,
        float* __restrict__ Zout,
        float* __restrict__ lastOut,
        int N)
{
    __shared__ __align__(16) float KT[LAYERS * C * C];   // KT[l][j][c] = K[l][c][j]
    __shared__ __align__(16) float sY[16][LC];           // per-warp Y staging
    for (int i = threadIdx.x; i < LAYERS * C * C; i += blockDim.x) {
        int l = i >> 10;
        int c = (i >> 5) & 31;
        int j = i & 31;
        KT[(l * C + j) * C + c] = K[i];
    }
    __syncthreads();

    const int lane = threadIdx.x & 31;
    const int warp = threadIdx.x >> 5;
    const int gwarp = blockIdx.x * (blockDim.x >> 5) + warp;
    const int nwarps = gridDim.x * (blockDim.x >> 5);
    const int l = lane >> 3;
    const int cBase = (lane & 7) * 4;
    const size_t NC = (size_t)N * C;

    for (int n = gwarp; n < N; n += nwarps) {
        // source row (this node's dZ), 4 halves per lane
        uint2 za = __ldg((const uint2*)(dZ + (size_t)n * LC) + lane);
        float2 a01 = __half22float2(*(const __half2*)&za.x);
        float2 a23 = __half22float2(*(const __half2*)&za.y);
        float a0 = a01.x, a1 = a01.y, a2 = a23.x, a3 = a23.y;

        float acc0 = 0.f, acc1 = 0.f, acc2 = 0.f, acc3 = 0.f;
        const int rs = __ldg(rowstart + n);
        const int re = __ldg(rowstart + n + 1);
#pragma unroll 4
        for (int p = rs; p < re; p++) {
            uint2 r = __ldg(rec + p);                  // broadcast across warp
            float w = __uint_as_float(r.y);
            uint2 zb = __ldg((const uint2*)(dZ + (size_t)r.x * LC) + lane);
            float2 b01 = __half22float2(*(const __half2*)&zb.x);
            float2 b23 = __half22float2(*(const __half2*)&zb.y);
            acc0 += silu_f(w * (a0 - b01.x));
            acc1 += silu_f(w * (a1 - b01.y));
            acc2 += silu_f(w * (a2 - b23.x));
            acc3 += silu_f(w * (a3 - b23.y));
        }

        // matvec: y[c] = sum_j acc[l][j] * KT[l][j][c]  (then negated)
        float av[4] = {acc0, acc1, acc2, acc3};
        u64 y01 = 0ULL, y23 = 0ULL;
#pragma unroll
        for (int j = 0; j < C; j++) {
            int src = (lane & 248) | (j >> 2);
            float bv = __shfl_sync(0xffffffffu, av[j & 3], src);
            u64 b2 = pack2(bv, bv);
            ulonglong2 w = *(const ulonglong2*)&KT[(l * C + j) * C + cBase];
            y01 = fma2(b2, w.x, y01);
            y23 = fma2(b2, w.y, y23);
        }
        float y0, y1, y2, y3;
        unpack2(y01, y0, y1);
        unpack2(y23, y2, y3);
        *(float4*)&sY[warp][lane * 4] = make_float4(-y0, -y1, -y2, -y3);
        __syncwarp();

        // channel-per-lane tridiagonal chain
        float Y0 = sY[warp][0 * C + lane];
        float Y1 = sY[warp][1 * C + lane];
        float Y2 = sY[warp][2 * C + lane];
        float Y3 = sY[warp][3 * C + lane] + __ldg(X + (size_t)n * C + lane);

        const float s12 = 0.70710678118654752f;
        const float s23 = 0.81649658092772603f;
        const float s34 = 0.86602540378443865f;
        const float s45 = 0.89442719099991588f;
        float t0 = s12 * Y0;
        float t1 = s23 * (s12 * t0 + Y1);
        float t2 = s34 * (s23 * t1 + Y2);
        float t3 = s45 * (s34 * t2 + Y3);
        float w3 = s45 * t3;
        float w2 = s34 * (s34 * w3 + t2);
        float w1 = s23 * (s23 * w2 + t1);
        float w0 = s12 * (s12 * w1 + t0);

        const size_t base = (size_t)n * C + lane;
        Zout[0 * NC + base] = w0;
        Zout[1 * NC + base] = w1;
        Zout[2 * NC + base] = w2;
        Zout[3 * NC + base] = w3;
        if (lastOut) lastOut[base] = w3;
        __syncwarp();   // sY reuse
    }
}

// ---------------------------------------------------------------------------
extern "C" void kernel_launch(void* const* d_in, const int* in_sizes, int n_in,
                              void* d_out, int out_size)
{
    const float* X  = (const float*)d_in[0];
    const float* f  = (const float*)d_in[1];
    const int*   ei = (const int*)d_in[2];
    const float* ew = (const float*)d_in[3];
    const float* K  = (const float*)d_in[4];
    const float* Kf = (const float*)d_in[5];

    const int N = in_sizes[0] / C;
    const int E = in_sizes[3];

    __half* dZ; float* Zb;
    uint2* rec; int *cnt, *S, *rowstart, *cursor, *bsum, *boff;
    cudaGetSymbolAddress((void**)&dZ,       g_dZ);
    cudaGetSymbolAddress((void**)&Zb,       g_Z);
    cudaGetSymbolAddress((void**)&rec,      g_rec);
    cudaGetSymbolAddress((void**)&cnt,      g_cnt);
    cudaGetSymbolAddress((void**)&S,        g_S);
    cudaGetSymbolAddress((void**)&rowstart, g_rowstart);
    cudaGetSymbolAddress((void**)&cursor,   g_cursor);
    cudaGetSymbolAddress((void**)&bsum,     g_bsum);
    cudaGetSymbolAddress((void**)&boff,     g_boff);

    const size_t NC = (size_t)N * C;
    float* out = (float*)d_out;
    float* Zfinal;
    float* lastPtr;
    if ((size_t)out_size >= (size_t)(LAYERS + 1) * NC) {
        lastPtr = out;            // Z[-1] first
        Zfinal  = out + NC;       // then full Z
    } else if ((size_t)out_size >= (size_t)LAYERS * NC) {
        Zfinal  = out;
        lastPtr = nullptr;
    } else {
        Zfinal  = Zb;
        lastPtr = out;
    }

    // ---- CSR build (once per launch, reused by both fixpoint iterations) ----
    const int scanBlocks = (N + 511) / 512;
    const int edgeBlocks = (E + 511) / 512;
    zero_cnt_kernel<<<scanBlocks, 512>>>(cnt, N);
    hist_kernel<<<edgeBlocks, 512>>>(ei, cnt, E);
    scan1_kernel<<<scanBlocks, 512>>>(cnt, S, bsum, N);
    scan2_kernel<<<1, 512>>>(bsum, boff, scanBlocks);
    scan3_kernel<<<scanBlocks, 512>>>(cnt, S, boff, rowstart, cursor, N);
    scatter_kernel<<<edgeBlocks, 512>>>(ei, ew, cursor, rec, E);

    dim3 nodeGrid((N + 255) / 256, LAYERS);
    const int fusedBlocks = 296;   // 2 per SM, 16 warps each

    for (int it = 0; it < NFIX; it++) {
        node_forward_kernel<<<nodeGrid, 256>>>(Zb, f, Kf, K, dZ, N, it > 0 ? 1 : 0);
        const bool last = (it == NFIX - 1);
        edge_tri_kernel<<<fusedBlocks, 512>>>(dZ, rec, rowstart, K, X,
                                              last ? Zfinal : Zb,
                                              last ? lastPtr : nullptr,
                                              N);
    }
}